// round 2
// baseline (speedup 1.0000x reference)
#include <cuda_runtime.h>
#include <stdint.h>

// im:  [B=16, H=512, W=512, C=3] float32, values in [0,1)
// it:  [B=16, I=256, C=3] float32 LUT
// out: [B,H,W,C] = it[b, rn(255*im), c]
//
// Pure streaming gather, HBM-bound. float4 I/O, per-batch LUT in smem.

#define B_DIM 16
#define PIX_PER_BATCH (512 * 512 * 3)      // 786432 floats
#define N4_PER_BATCH (PIX_PER_BATCH / 4)   // 196608 float4
#define LUT_FLOATS (256 * 3)               // 768
#define THREADS 256
#define BLOCKS_PER_BATCH 96                // 96*256*8 == 196608

__device__ __forceinline__ int qidx(float v) {
    int i = __float2int_rn(255.0f * v);    // round-to-nearest-even, matches jnp.round
    i = max(i, 0);
    i = min(i, 255);
    return i;
}

__global__ void __launch_bounds__(THREADS)
intensity_transform_kernel(const float* __restrict__ im,
                           const float* __restrict__ it,
                           float* __restrict__ out) {
    __shared__ float lut[LUT_FLOATS];      // layout: lut[3*idx + c]

    const int b = blockIdx.y;
    const float* __restrict__ itb = it + (size_t)b * LUT_FLOATS;

    // Cooperative LUT load (3 floats per thread)
    for (int i = threadIdx.x; i < LUT_FLOATS; i += THREADS) {
        lut[i] = itb[i];
    }
    __syncthreads();

    const float4* __restrict__ in4 =
        reinterpret_cast<const float4*>(im + (size_t)b * PIX_PER_BATCH);
    float4* __restrict__ out4 =
        reinterpret_cast<float4*>(out + (size_t)b * PIX_PER_BATCH);

    const int stride = gridDim.x * THREADS;   // 24576

    // 8 iterations per thread; unroll 4 to front-batch LDG.128s (MLP).
    #pragma unroll 4
    for (int t = blockIdx.x * THREADS + threadIdx.x; t < N4_PER_BATCH; t += stride) {
        float4 v = in4[t];

        // channel of component j is (4t + j) % 3 == (t + j) % 3
        int c0 = t % 3;
        int c1 = c0 + 1; if (c1 == 3) c1 = 0;
        int c2 = c1 + 1; if (c2 == 3) c2 = 0;
        // component 3 wraps back to c0

        float4 r;
        r.x = lut[3 * qidx(v.x) + c0];
        r.y = lut[3 * qidx(v.y) + c1];
        r.z = lut[3 * qidx(v.z) + c2];
        r.w = lut[3 * qidx(v.w) + c0];

        out4[t] = r;
    }
}

extern "C" void kernel_launch(void* const* d_in, const int* in_sizes, int n_in,
                              void* d_out, int out_size) {
    const float* im = (const float*)d_in[0];
    const float* it = (const float*)d_in[1];
    float* out = (float*)d_out;

    dim3 grid(BLOCKS_PER_BATCH, B_DIM);
    intensity_transform_kernel<<<grid, THREADS>>>(im, it, out);
}

// round 5
// speedup vs baseline: 1.1848x; 1.1848x over previous
#include <cuda_runtime.h>
#include <stdint.h>

// im:  [B=16, H=512, W=512, C=3] float32, values in [0,1)
// it:  [B=16, I=256, C=3] float32 LUT
// out: [B,H,W,C] = it[b, rn(255*im), c]
//
// HBM/L2-bound streaming gather. float4 I/O, per-batch LUT in smem.
// Grid sized to EXACTLY one wave: 8 CTAs/SM x 148 SMs = 1184 CTAs = (74, 16).

#define B_DIM 16
#define PIX_PER_BATCH (512 * 512 * 3)      // 786432 floats
#define N4_PER_BATCH (PIX_PER_BATCH / 4)   // 196608 float4
#define LUT_FLOATS (256 * 3)               // 768
#define THREADS 256
#define BLOCKS_PER_BATCH 74                // 74*16 = 1184 CTAs = one full wave @ 8 CTA/SM

__device__ __forceinline__ int qidx(float v) {
    int i = __float2int_rn(255.0f * v);    // round-to-nearest-even, matches jnp.round
    i = max(i, 0);
    i = min(i, 255);
    return i;
}

__global__ void __launch_bounds__(THREADS)
intensity_transform_kernel(const float* __restrict__ im,
                           const float* __restrict__ it,
                           float* __restrict__ out) {
    __shared__ float lut[LUT_FLOATS];      // layout: lut[3*idx + c]

    const int b = blockIdx.y;
    const float* __restrict__ itb = it + (size_t)b * LUT_FLOATS;

    // Cooperative LUT load (3 floats per thread)
    for (int i = threadIdx.x; i < LUT_FLOATS; i += THREADS) {
        lut[i] = itb[i];
    }
    __syncthreads();

    const float4* __restrict__ in4 =
        reinterpret_cast<const float4*>(im + (size_t)b * PIX_PER_BATCH);
    float4* __restrict__ out4 =
        reinterpret_cast<float4*>(out + (size_t)b * PIX_PER_BATCH);

    const int stride = BLOCKS_PER_BATCH * THREADS;   // 18944

    // ~10.4 iterations per thread; unroll 4 to front-batch LDG.128s (MLP).
    #pragma unroll 4
    for (int t = blockIdx.x * THREADS + threadIdx.x; t < N4_PER_BATCH; t += stride) {
        float4 v = in4[t];

        // channel of component j is (4t + j) % 3 == (t + j) % 3
        int c0 = t % 3;
        int c1 = c0 + 1; if (c1 == 3) c1 = 0;
        int c2 = c1 + 1; if (c2 == 3) c2 = 0;
        // component 3 wraps back to c0

        float4 r;
        r.x = lut[3 * qidx(v.x) + c0];
        r.y = lut[3 * qidx(v.y) + c1];
        r.z = lut[3 * qidx(v.z) + c2];
        r.w = lut[3 * qidx(v.w) + c0];

        out4[t] = r;
    }
}

extern "C" void kernel_launch(void* const* d_in, const int* in_sizes, int n_in,
                              void* d_out, int out_size) {
    const float* im = (const float*)d_in[0];
    const float* it = (const float*)d_in[1];
    float* out = (float*)d_out;

    dim3 grid(BLOCKS_PER_BATCH, B_DIM);
    intensity_transform_kernel<<<grid, THREADS>>>(im, it, out);
}

// round 6
// speedup vs baseline: 1.2471x; 1.0525x over previous
#include <cuda_runtime.h>
#include <stdint.h>

// im:  [B=16, H=512, W=512, C=3] float32 in [0,1); it: [B,256,3] LUT
// out[b,h,w,c] = it[b, rn(255*im[b,h,w,c]), c]
//
// Latency-limited streaming gather. One-wave grid (1184 CTAs), float4 I/O,
// per-batch smem LUT, ILP-2 paired iterations, streaming stores.

#define B_DIM 16
#define PIX_PER_BATCH (512 * 512 * 3)      // 786432 floats
#define N4_PER_BATCH (PIX_PER_BATCH / 4)   // 196608 float4
#define LUT_FLOATS (256 * 3)               // 768
#define THREADS 256
#define BLOCKS_PER_BATCH 74                // 74*16 = 1184 CTAs = one wave @ 8 CTA/SM
#define STRIDE (BLOCKS_PER_BATCH * THREADS) // 18944 (mod 3 == 2)

__device__ __forceinline__ int qidx(float v) {
    int i = __float2int_rn(255.0f * v);    // RNE, matches jnp.round on same product
    i = max(i, 0);
    i = min(i, 255);
    return i;
}

__device__ __forceinline__ float4 lookup4(const float* __restrict__ lut,
                                          float4 v, int t) {
    // channel of component j of float4 t is (4t+j) % 3 == (t+j) % 3
    int c0 = t % 3;
    int c1 = c0 + 1; if (c1 == 3) c1 = 0;
    int c2 = c1 + 1; if (c2 == 3) c2 = 0;
    float4 r;
    r.x = lut[3 * qidx(v.x) + c0];
    r.y = lut[3 * qidx(v.y) + c1];
    r.z = lut[3 * qidx(v.z) + c2];
    r.w = lut[3 * qidx(v.w) + c0];
    return r;
}

__global__ void __launch_bounds__(THREADS)
intensity_transform_kernel(const float* __restrict__ im,
                           const float* __restrict__ it,
                           float* __restrict__ out) {
    __shared__ float lut[LUT_FLOATS];      // layout: lut[3*idx + c]

    const int b = blockIdx.y;
    const float* __restrict__ itb = it + (size_t)b * LUT_FLOATS;

    for (int i = threadIdx.x; i < LUT_FLOATS; i += THREADS) {
        lut[i] = itb[i];
    }
    __syncthreads();

    const float4* __restrict__ in4 =
        reinterpret_cast<const float4*>(im + (size_t)b * PIX_PER_BATCH);
    float4* __restrict__ out4 =
        reinterpret_cast<float4*>(out + (size_t)b * PIX_PER_BATCH);

    int t = blockIdx.x * THREADS + threadIdx.x;

    // Uniform 5 pair-iterations per thread (2*STRIDE*5 + tail covers N4).
    // Two independent LDG->LDS->STG chains per iteration; unroll 2 => 4 LDGs in flight.
    #pragma unroll 2
    for (; t + STRIDE < N4_PER_BATCH; t += 2 * STRIDE) {
        float4 v0 = in4[t];
        float4 v1 = in4[t + STRIDE];
        float4 r0 = lookup4(lut, v0, t);
        float4 r1 = lookup4(lut, v1, t + STRIDE);
        __stcs(&out4[t], r0);
        __stcs(&out4[t + STRIDE], r1);
    }
    // Tail: threads with base < N4 - 10*STRIDE (= 7168) do one more float4.
    if (t < N4_PER_BATCH) {
        float4 v = in4[t];
        float4 r = lookup4(lut, v, t);
        __stcs(&out4[t], r);
    }
}

extern "C" void kernel_launch(void* const* d_in, const int* in_sizes, int n_in,
                              void* d_out, int out_size) {
    const float* im = (const float*)d_in[0];
    const float* it = (const float*)d_in[1];
    float* out = (float*)d_out;

    dim3 grid(BLOCKS_PER_BATCH, B_DIM);
    intensity_transform_kernel<<<grid, THREADS>>>(im, it, out);
}